// round 13
// baseline (speedup 1.0000x reference)
#include <cuda_runtime.h>
#include <cuda_fp16.h>
#include <cstdint>
#include <math.h>

#define BB   256
#define DD   1024
#define HH   8
#define HDIM 128
#define PP   2048
#define HIDD 1024
#define KW   4
#define EPSF 1e-5f

// mma.sync GEMM tiling: CTA 16x64, 4 warps (1m x 4n), warp tile 16x16
#define TBM  16
#define TBN  64
#define TBK  32
#define SOFF_AH 0
#define SOFF_AL 1024
#define SOFF_B  2048
#define STAGE_B 6144
#define NSTAGE  4
#define DYN_SMEM (NSTAGE*STAGE_B + 128)

// ---------------- scratch (device globals; no allocation allowed) ----------
__device__ float g_rt [BB*HIDD];
__device__ float g_xc [BB*PP];
__device__ float g_q  [BB*HIDD];
__device__ float g_k  [BB*HIDD];
__device__ float g_v  [BB*HIDD];
__device__ float g_o  [BB*HIDD];
__device__ float g_sk [BB*HIDD];

// fp16 operands (16B-aligned for cp.async)
#define WTOT 14680064
__device__ __align__(256) __half g_wf[WTOT];                 // weights, single fp16
__device__ __align__(256) __half g_xnh[BB*DD],  g_xnl[BB*DD];
__device__ __align__(256) __half g_xth[BB*PP],  g_xtl[BB*PP];
__device__ __align__(256) __half g_xch[BB*PP],  g_xcl[BB*PP];
__device__ __align__(256) __half g_yh [BB*HIDD], g_yl[BB*HIDD];

// weight offsets (elements) in g_wf
#define OFF_UPL  0u
#define OFF_UPR  2097152u
#define OFF_Q    3145728u
#define OFF_K    5242880u
#define OFF_V    7340032u
#define OFF_O    9437184u
#define OFF_SKIP 11534336u
#define OFF_DOWN 13631488u

// ---------------- PTX helpers ----------------------------------------------
__device__ __forceinline__ uint32_t smem_u32(const void* p) {
    uint32_t a;
    asm("{ .reg .u64 t; cvta.to.shared.u64 t, %1; cvt.u32.u64 %0, t; }" : "=r"(a) : "l"(p));
    return a;
}
__device__ __forceinline__ void cp16(uint32_t dst, const void* src) {
    asm volatile("cp.async.cg.shared.global [%0], [%1], 16;" :: "r"(dst), "l"(src));
}
#define CP_COMMIT() asm volatile("cp.async.commit_group;" ::: "memory")
#define CP_WAIT2()  asm volatile("cp.async.wait_group 2;" ::: "memory")
#define CP_WAIT1()  asm volatile("cp.async.wait_group 1;" ::: "memory")
#define CP_WAIT0()  asm volatile("cp.async.wait_group 0;" ::: "memory")

__device__ __forceinline__ void ldsm4(uint32_t* r, uint32_t addr) {
    asm volatile("ldmatrix.sync.aligned.m8n8.x4.shared.b16 {%0,%1,%2,%3}, [%4];"
                 : "=r"(r[0]), "=r"(r[1]), "=r"(r[2]), "=r"(r[3]) : "r"(addr));
}
__device__ __forceinline__ void mma16816(float* c, const uint32_t* a, uint32_t b0, uint32_t b1) {
    asm volatile(
        "mma.sync.aligned.m16n8k16.row.col.f32.f16.f16.f32 "
        "{%0,%1,%2,%3}, {%4,%5,%6,%7}, {%8,%9}, {%0,%1,%2,%3};"
        : "+f"(c[0]), "+f"(c[1]), "+f"(c[2]), "+f"(c[3])
        : "r"(a[0]), "r"(a[1]), "r"(a[2]), "r"(a[3]), "r"(b0), "r"(b1));
}

// chunk-XOR swizzle: 64B rows, 4 chunks of 16B, conflict-free for ldmatrix
__device__ __forceinline__ uint32_t swz(int r, int c) {
    return (uint32_t)(r * 64 + ((c ^ ((r >> 1) & 3)) * 16));
}

__device__ __forceinline__ void split1(float v, __half& h, __half& l) {
    h = __float2half(v);
    l = __float2half(v - __half2float(h));
}

// ---------------- tensor GEMM (mma.sync fp16 x2-split) ----------------------
struct TSeg {
    const __half *Xh, *Xl;   // [M, K] activation hi/lo
    const __half *W;         // [N, K] fp16 weights
    const float* bias;
    const float* resid;
    float* Y;                // fp32 out (nullable)
    __half *Yh, *Yl;         // optional split out (nullable)
    float scale;
    int act;      // 1 = sigmoid
    int nblk;     // N / TBN
    int N;
};
struct TArgs { TSeg s[5]; int nseg; int K; };

__device__ __forceinline__ void load_stage(uint32_t sb,
        const __half* axh, const __half* axl,
        const __half* bw,
        int K, int kbase, int tid) {
    // A: 16 rows x 4 chunks = 64 chunk loads per operand (threads 0-63)
    if (tid < 64) {
        int row = tid >> 2, c = tid & 3;
        uint32_t o = swz(row, c);
        const size_t g = (size_t)row * K + kbase + c * 8;
        cp16(sb + SOFF_AH + o, axh + g);
        cp16(sb + SOFF_AL + o, axl + g);
    }
    // B: 64 rows x 4 chunks = 256 chunk loads (2 per thread)
#pragma unroll
    for (int i = 0; i < 2; i++) {
        int idx = tid + 128 * i;
        int row = idx >> 2, c = idx & 3;
        uint32_t o = swz(row, c);
        const size_t g = (size_t)row * K + kbase + c * 8;
        cp16(sb + SOFF_B + o, bw + g);
    }
}

__global__ __launch_bounds__(128)
void tgemm(TArgs args) {
    extern __shared__ char dyn[];
    uint32_t sb = smem_u32(dyn);
    sb = (sb + 127) & ~127u;

    int nb = blockIdx.x, si = 0;
    while (si < args.nseg - 1 && nb >= args.s[si].nblk) { nb -= args.s[si].nblk; si++; }
    const TSeg sg = args.s[si];
    const int K = args.K;
    const int bm = blockIdx.y;

    int tid = threadIdx.x;
    int wn = tid >> 5, lane = tid & 31;   // 4 warps along N (16 each)

    const __half* axh = sg.Xh + (size_t)bm * TBM * K;
    const __half* axl = sg.Xl + (size_t)bm * TBM * K;
    const __half* bw  = sg.W  + (size_t)nb * TBN * K;

    float acc[2][4];
#pragma unroll
    for (int j = 0; j < 2; j++)
#pragma unroll
        for (int l = 0; l < 4; l++) acc[j][l] = 0.f;

    const int T = K / TBK;

    load_stage(sb, axh, axl, bw, K, 0, tid);
    CP_COMMIT();
    load_stage(sb + STAGE_B, axh, axl, bw, K, TBK, tid);
    CP_COMMIT();

    int lr = lane & 15, lch = lane >> 4;

    for (int t = 0; t < T; t++) {
        uint32_t cur = sb + (t & 3) * STAGE_B;
        if (t + 2 < T) {
            load_stage(sb + ((t + 2) & 3) * STAGE_B, axh, axl, bw, K, (t + 2) * TBK, tid);
            CP_COMMIT();
            CP_WAIT2();
        } else if (t + 1 < T) {
            CP_WAIT1();
        } else {
            CP_WAIT0();
        }
        __syncthreads();
        // single barrier: write stage (t+2)&3 is distance 3 (mod 4) from the
        // slowest possible reader stage (t-1)&3 — never collides.

#pragma unroll
        for (int kk = 0; kk < 2; kk++) {
            int c = kk * 2 + lch;
            uint32_t Ah[4], Al[4];
            {
                uint32_t o = swz(lr, c);
                ldsm4(Ah, cur + SOFF_AH + o);
                ldsm4(Al, cur + SOFF_AL + o);
            }
            uint32_t Bf[4];
            {
                int r = wn * 16 + lr;
                uint32_t o = swz(r, c);
                ldsm4(Bf, cur + SOFF_B + o);
            }
#pragma unroll
            for (int inn = 0; inn < 2; inn++) {
                uint32_t b0 = Bf[inn], b1 = Bf[inn + 2];
                mma16816(acc[inn], Ah, b0, b1);
                mma16816(acc[inn], Al, b0, b1);
            }
        }
    }

    int group = lane >> 2, tig = lane & 3;
#pragma unroll
    for (int inn = 0; inn < 2; inn++) {
        int mrow = bm * TBM + group;
        int col  = nb * TBN + wn * 16 + inn * 8 + tig * 2;
#pragma unroll
        for (int half = 0; half < 2; half++) {
            int row = mrow + half * 8;
            float2 v;
            v.x = acc[inn][half * 2 + 0];
            v.y = acc[inn][half * 2 + 1];
            if (sg.bias) { v.x += sg.bias[col]; v.y += sg.bias[col + 1]; }
            v.x *= sg.scale; v.y *= sg.scale;
            if (sg.act == 1) {
                v.x = 1.f / (1.f + expf(-v.x));
                v.y = 1.f / (1.f + expf(-v.y));
            }
            if (sg.resid) {
                const float2 rv = *(const float2*)&sg.resid[(size_t)row * sg.N + col];
                v.x += rv.x; v.y += rv.y;
            }
            size_t off = (size_t)row * sg.N + col;
            if (sg.Y) *(float2*)&sg.Y[off] = v;
            if (sg.Yh) {
                __half h0, l0, h1, l1;
                split1(v.x, h0, l0);
                split1(v.y, h1, l1);
                *(__half2*)&sg.Yh[off] = __half2(h0, h1);
                *(__half2*)&sg.Yl[off] = __half2(l0, l1);
            }
        }
    }
}

// ---------------- fp32 -> fp16 weight convert --------------------------------
struct SSeg { const float* src; __half* dst; int nblk; };
struct SArgs { SSeg s[8]; int nseg; };

__global__ void split_kernel(SArgs a) {
    int b = blockIdx.x, si = 0;
    while (si < a.nseg - 1 && b >= a.s[si].nblk) { b -= a.s[si].nblk; si++; }
    const SSeg sg = a.s[si];
    int i = b * 256 + threadIdx.x;          // index of float4
    float4 v = ((const float4*)sg.src)[i];
    __half2* pd = (__half2*)(sg.dst + (size_t)i * 4);
    pd[0] = __half2(__float2half(v.x), __float2half(v.y));
    pd[1] = __half2(__float2half(v.z), __float2half(v.w));
}

// ---------------- LayerNorm (emits fp16 hi/lo directly) ----------------------
__global__ void ln_kernel(const float* __restrict__ x,
                          const float* __restrict__ w,
                          const float* __restrict__ b) {
    int row = blockIdx.x;
    const float* xr = x + row * DD;
    float s = 0.f, s2 = 0.f;
    for (int i = threadIdx.x; i < DD; i += blockDim.x) {
        float v = xr[i]; s += v; s2 += v * v;
    }
    __shared__ float rs[32], rs2[32];
    for (int o = 16; o; o >>= 1) {
        s  += __shfl_xor_sync(0xffffffffu, s,  o);
        s2 += __shfl_xor_sync(0xffffffffu, s2, o);
    }
    int wr = threadIdx.x >> 5, ln = threadIdx.x & 31;
    if (ln == 0) { rs[wr] = s; rs2[wr] = s2; }
    __syncthreads();
    if (wr == 0) {
        int nw = blockDim.x >> 5;
        s  = (ln < nw) ? rs[ln]  : 0.f;
        s2 = (ln < nw) ? rs2[ln] : 0.f;
        for (int o = 16; o; o >>= 1) {
            s  += __shfl_xor_sync(0xffffffffu, s,  o);
            s2 += __shfl_xor_sync(0xffffffffu, s2, o);
        }
        if (ln == 0) { rs[0] = s; rs2[0] = s2; }
    }
    __syncthreads();
    float mu  = rs[0] / (float)DD;
    float var = rs2[0] / (float)DD - mu * mu;
    float r   = rsqrtf(var + EPSF);
    for (int i = threadIdx.x; i < DD; i += blockDim.x) {
        float v = (xr[i] - mu) * r * w[i] + b[i];
        __half h, l;
        split1(v, h, l);
        g_xnh[row * DD + i] = h;
        g_xnl[row * DD + i] = l;
    }
}

// ---------------- causal conv (K=4) + SiLU (reads xth+xtl) -------------------
__global__ void conv_kernel(const float* __restrict__ cw,
                            const float* __restrict__ cb) {
    int idx = blockIdx.x * blockDim.x + threadIdx.x;
    int b = idx / PP, p = idx % PP;
    const __half* xh = g_xth + (size_t)b * PP;
    const __half* xl = g_xtl + (size_t)b * PP;
    float s = *cb;
#pragma unroll
    for (int j = 0; j < KW; j++) {
        int src = p + j - (KW - 1);
        if (src >= 0)
            s += cw[j] * (__half2float(xh[src]) + __half2float(xl[src]));
    }
    float v = s / (1.f + expf(-s));
    g_xc[idx] = v;
    __half h, l;
    split1(v, h, l);
    g_xch[idx] = h;
    g_xcl[idx] = l;
}

// ---- cell: i/f gates, c_t, n_t, num/den, o-gate, GroupNorm, mix (fused) ----
__global__ void cell_kernel(const float* __restrict__ c_in,
                            const float* __restrict__ n_in,
                            const float* __restrict__ m_in,
                            const float* __restrict__ gnw,
                            const float* __restrict__ gnb,
                            const float* __restrict__ Wi, const float* __restrict__ bi,
                            const float* __restrict__ Wf, const float* __restrict__ bf,
                            float* __restrict__ c_out,
                            float* __restrict__ n_out,
                            float* __restrict__ m_out) {
    int bh = blockIdx.x;
    int b = bh >> 3, h = bh & 7;
    __shared__ float sq[HDIM], sk[HDIM], sv[HDIM], sh[HDIM];
    __shared__ float s_red[16];
    __shared__ float s_ig, s_fg, s_den, s_mu, s_rstd;
    int tid = threadIdx.x;
    int warp = tid >> 5, lane = tid & 31;

    if (tid < HDIM) {
        int off = b * HIDD + h * HDIM + tid;
        sq[tid] = g_q[off]; sk[tid] = g_k[off]; sv[tid] = g_v[off];
    }

    // fused i/f dot products over PP (exact fp32)
    {
        const float* xc = g_xc + (size_t)b * PP;
        const float* wi = Wi + (size_t)h * PP;
        const float* wf = Wf + (size_t)h * PP;
        float pi = 0.f, pf = 0.f;
#pragma unroll
        for (int j = tid; j < PP; j += 256) {
            float x = xc[j];
            pi += x * wi[j];
            pf += x * wf[j];
        }
        for (int o = 16; o; o >>= 1) {
            pi += __shfl_xor_sync(0xffffffffu, pi, o);
            pf += __shfl_xor_sync(0xffffffffu, pf, o);
        }
        if (lane == 0) { s_red[warp] = pi; s_red[8 + warp] = pf; }
    }
    __syncthreads();
    if (tid == 0) {
        float it = s_red[0]+s_red[1]+s_red[2]+s_red[3]+s_red[4]+s_red[5]+s_red[6]+s_red[7] + bi[h];
        float ft = s_red[8]+s_red[9]+s_red[10]+s_red[11]+s_red[12]+s_red[13]+s_red[14]+s_red[15] + bf[h];
        float m0 = m_in[bh];
        float mt = fmaxf(ft + m0, it);
        s_ig = expf(it - mt);
        s_fg = expf(ft - mt + m0);
        m_out[bh] = mt;
    }
    __syncthreads();
    float ig = s_ig, fg = s_fg;

    float dp = 0.f;
    if (tid < HDIM) {
        float nt = fg * n_in[(size_t)bh * HDIM + tid] + ig * sk[tid];
        n_out[(size_t)bh * HDIM + tid] = nt;
        dp = nt * sq[tid];
    }
    for (int o = 16; o; o >>= 1) dp += __shfl_xor_sync(0xffffffffu, dp, o);
    if (lane == 0) s_red[warp] = dp;
    __syncthreads();
    if (tid == 0)
        s_den = fmaxf(s_red[0] + s_red[1] + s_red[2] + s_red[3], 1.0f);

    float4 kv = ((const float4*)sk)[lane];
    float4 qv = ((const float4*)sq)[lane];
    size_t base = (size_t)bh * HDIM * HDIM;
#pragma unroll
    for (int it2 = 0; it2 < 8; it2++) {
        int d0 = warp + it2 * 16;
        int d1 = d0 + 8;
        const float4* s0 = (const float4*)(c_in + base + (size_t)d0 * HDIM);
        const float4* s1 = (const float4*)(c_in + base + (size_t)d1 * HDIM);
        float4*       t0 = (float4*)(c_out + base + (size_t)d0 * HDIM);
        float4*       t1 = (float4*)(c_out + base + (size_t)d1 * HDIM);
        float i0 = ig * sv[d0], i1 = ig * sv[d1];
        float4 c0 = s0[lane], c1 = s1[lane];
        float4 n0, n1;
        n0.x = fg * c0.x + i0 * kv.x; n1.x = fg * c1.x + i1 * kv.x;
        n0.y = fg * c0.y + i0 * kv.y; n1.y = fg * c1.y + i1 * kv.y;
        n0.z = fg * c0.z + i0 * kv.z; n1.z = fg * c1.z + i1 * kv.z;
        n0.w = fg * c0.w + i0 * kv.w; n1.w = fg * c1.w + i1 * kv.w;
        t0[lane] = n0; t1[lane] = n1;
        float a0 = n0.x * qv.x + n0.y * qv.y + n0.z * qv.z + n0.w * qv.w;
        float a1 = n1.x * qv.x + n1.y * qv.y + n1.z * qv.z + n1.w * qv.w;
        for (int o = 16; o; o >>= 1) {
            a0 += __shfl_xor_sync(0xffffffffu, a0, o);
            a1 += __shfl_xor_sync(0xffffffffu, a1, o);
        }
        if (lane == 0) { sh[d0] = a0; sh[d1] = a1; }
    }
    __syncthreads();

    float hv = 0.f;
    if (tid < HDIM)
        hv = g_o[b * HIDD + h * HDIM + tid] * sh[tid] / s_den;
    float s1 = hv, s2 = hv * hv;
    for (int o = 16; o; o >>= 1) {
        s1 += __shfl_xor_sync(0xffffffffu, s1, o);
        s2 += __shfl_xor_sync(0xffffffffu, s2, o);
    }
    if (lane == 0) { s_red[warp] = s1; s_red[8 + warp] = s2; }
    __syncthreads();
    if (tid == 0) {
        float m1 = (s_red[0] + s_red[1] + s_red[2] + s_red[3]) / (float)HDIM;
        float m2 = (s_red[8] + s_red[9] + s_red[10] + s_red[11]) / (float)HDIM;
        s_mu = m1;
        s_rstd = rsqrtf(m2 - m1 * m1 + EPSF);
    }
    __syncthreads();
    if (tid < HDIM) {
        int c = h * HDIM + tid;
        int gi = b * HIDD + c;
        float hn = (hv - s_mu) * s_rstd * gnw[c] + gnb[c];
        float r = g_rt[gi];
        float y = (hn + g_sk[gi]) * (r / (1.f + expf(-r)));
        __half yh, yl;
        split1(y, yh, yl);
        g_yh[gi] = yh;
        g_yl[gi] = yl;
    }
}

// ---------------- host ---------------------------------------------------------
static void* sym_addr(const void* sym) {
    void* p = nullptr;
    cudaGetSymbolAddress(&p, sym);
    return p;
}

extern "C" void kernel_launch(void* const* d_in, const int* in_sizes, int n_in,
                              void* d_out, int out_size) {
    const float* seq    = (const float*)d_in[0];
    const float* c_tm1  = (const float*)d_in[1];
    const float* n_tm1  = (const float*)d_in[2];
    const float* m_tm1  = (const float*)d_in[3];
    const float* ln_w   = (const float*)d_in[4];
    const float* ln_b   = (const float*)d_in[5];
    const float* gn_w   = (const float*)d_in[6];
    const float* gn_b   = (const float*)d_in[7];
    const float* up_l_w = (const float*)d_in[8];
    const float* up_l_b = (const float*)d_in[9];
    const float* up_r_w = (const float*)d_in[10];
    const float* up_r_b = (const float*)d_in[11];
    const float* down_w = (const float*)d_in[12];
    const float* down_b = (const float*)d_in[13];
    const float* Wi_w   = (const float*)d_in[14];
    const float* Wi_b   = (const float*)d_in[15];
    const float* Wf_w   = (const float*)d_in[16];
    const float* Wf_b   = (const float*)d_in[17];
    const float* Wo_w   = (const float*)d_in[18];
    const float* Wo_b   = (const float*)d_in[19];
    const float* Wq_w   = (const float*)d_in[20];
    const float* Wq_b   = (const float*)d_in[21];
    const float* Wk_w   = (const float*)d_in[22];
    const float* Wk_b   = (const float*)d_in[23];
    const float* Wv_w   = (const float*)d_in[24];
    const float* Wv_b   = (const float*)d_in[25];
    const float* conv_w = (const float*)d_in[26];
    const float* conv_b = (const float*)d_in[27];
    const float* skip_w = (const float*)d_in[28];

    float* out   = (float*)d_out;
    float* c_out = out + (size_t)BB * DD;
    float* n_out = c_out + (size_t)BB * HH * HDIM * HDIM;
    float* m_out = n_out + (size_t)BB * HH * HDIM;

    float* p_rt = (float*)sym_addr(g_rt);
    float* p_q  = (float*)sym_addr(g_q);
    float* p_k  = (float*)sym_addr(g_k);
    float* p_v  = (float*)sym_addr(g_v);
    float* p_o  = (float*)sym_addr(g_o);
    float* p_sk = (float*)sym_addr(g_sk);

    __half* wf  = (__half*)sym_addr(g_wf);
    __half* xnh = (__half*)sym_addr(g_xnh);
    __half* xnl = (__half*)sym_addr(g_xnl);
    __half* xth = (__half*)sym_addr(g_xth);
    __half* xtl = (__half*)sym_addr(g_xtl);
    __half* xch = (__half*)sym_addr(g_xch);
    __half* xcl = (__half*)sym_addr(g_xcl);
    __half* yh  = (__half*)sym_addr(g_yh);
    __half* yl  = (__half*)sym_addr(g_yl);

    cudaFuncSetAttribute(tgemm, cudaFuncAttributeMaxDynamicSharedMemorySize, DYN_SMEM);

    // side stream + events for overlapping the weight conversion (created once;
    // the launched work is identical on every call)
    static cudaStream_t s2 = nullptr;
    static cudaEvent_t eFork = nullptr, e1 = nullptr, e2 = nullptr;
    if (s2 == nullptr) {
        cudaStreamCreateWithFlags(&s2, cudaStreamNonBlocking);
        cudaEventCreateWithFlags(&eFork, cudaEventDisableTiming);
        cudaEventCreateWithFlags(&e1, cudaEventDisableTiming);
        cudaEventCreateWithFlags(&e2, cudaEventDisableTiming);
    }

    const float kscale = 1.0f / sqrtf((float)HDIM);

    // fork side stream from main
    cudaEventRecord(eFork, 0);
    cudaStreamWaitEvent(s2, eFork, 0);

    // side stream: convert up_l/up_r weights first (needed by stage1), then the rest
    {
        SArgs a; a.nseg = 2;
        a.s[0] = { up_l_w, wf + OFF_UPL, 2048 };
        a.s[1] = { up_r_w, wf + OFF_UPR, 1024 };
        split_kernel<<<3072, 256, 0, s2>>>(a);
        cudaEventRecord(e1, s2);
    }
    {
        SArgs a; a.nseg = 6;
        a.s[0] = { Wq_w,   wf + OFF_Q,    2048 };
        a.s[1] = { Wk_w,   wf + OFF_K,    2048 };
        a.s[2] = { Wv_w,   wf + OFF_V,    2048 };
        a.s[3] = { Wo_w,   wf + OFF_O,    2048 };
        a.s[4] = { skip_w, wf + OFF_SKIP, 2048 };
        a.s[5] = { down_w, wf + OFF_DOWN, 1024 };
        split_kernel<<<11264, 256, 0, s2>>>(a);
        cudaEventRecord(e2, s2);
    }

    // main stream: LayerNorm -> xnh/xnl (overlaps split #1)
    ln_kernel<<<BB, 256>>>(seq, ln_w, ln_b);

    // stage1 needs up_l/up_r weights
    cudaStreamWaitEvent(0, e1, 0);
    {
        TArgs a; a.nseg = 2; a.K = DD;
        a.s[0] = { xnh, xnl, wf + OFF_UPL, up_l_b, nullptr, nullptr, xth, xtl, 1.f, 0, PP / TBN,   PP   };
        a.s[1] = { xnh, xnl, wf + OFF_UPR, up_r_b, nullptr, p_rt, nullptr, nullptr, 1.f, 0, HIDD / TBN, HIDD };
        tgemm<<<dim3(PP / TBN + HIDD / TBN, BB / TBM), 128, DYN_SMEM>>>(a);
    }

    // causal conv + SiLU -> xc fp32 + xch/xcl (overlaps split #2)
    conv_kernel<<<(BB * PP) / 256, 256>>>(conv_w, conv_b);

    // stage2 needs the remaining weights
    cudaStreamWaitEvent(0, e2, 0);
    {
        TArgs a; a.nseg = 5; a.K = PP;
        a.s[0] = { xch, xcl, wf + OFF_Q,    Wq_b,    nullptr, p_q,  nullptr, nullptr, 1.f,    0, HIDD / TBN, HIDD };
        a.s[1] = { xch, xcl, wf + OFF_K,    Wk_b,    nullptr, p_k,  nullptr, nullptr, kscale, 0, HIDD / TBN, HIDD };
        a.s[2] = { xth, xtl, wf + OFF_V,    Wv_b,    nullptr, p_v,  nullptr, nullptr, 1.f,    0, HIDD / TBN, HIDD };
        a.s[3] = { xth, xtl, wf + OFF_O,    Wo_b,    nullptr, p_o,  nullptr, nullptr, 1.f,    1, HIDD / TBN, HIDD };
        a.s[4] = { xch, xcl, wf + OFF_SKIP, nullptr, nullptr, p_sk, nullptr, nullptr, 1.f,    0, HIDD / TBN, HIDD };
        tgemm<<<dim3(5 * (HIDD / TBN), BB / TBM), 128, DYN_SMEM>>>(a);
    }

    // cell update (+i/f gates, +groupnorm, +mix) -> yh/yl
    cell_kernel<<<BB * HH, 256>>>(c_tm1, n_tm1, m_tm1, gn_w, gn_b,
                                  Wi_w, Wi_b, Wf_w, Wf_b,
                                  c_out, n_out, m_out);

    // down projection + bias + residual
    {
        TArgs a; a.nseg = 1; a.K = HIDD;
        a.s[0] = { yh, yl, wf + OFF_DOWN, down_b, seq, out, nullptr, nullptr, 1.f, 0, DD / TBN, DD };
        tgemm<<<dim3(DD / TBN, BB / TBM), 128, DYN_SMEM>>>(a);
    }
}

// round 14
// speedup vs baseline: 1.1221x; 1.1221x over previous
#include <cuda_runtime.h>
#include <cuda_fp16.h>
#include <cstdint>
#include <math.h>

#define BB   256
#define DD   1024
#define HH   8
#define HDIM 128
#define PP   2048
#define HIDD 1024
#define KW   4
#define EPSF 1e-5f

// mma.sync GEMM tiling: CTA 16x128, 4 warps (1m x 4n), warp tile 16x32
#define TBM  16
#define TBN  128
#define TBK  32
#define SOFF_A  0
#define SOFF_B  1024
#define STAGE_B 9216
#define NSTAGE  4
#define DYN_SMEM (NSTAGE*STAGE_B + 128)

// ---------------- scratch (device globals; no allocation allowed) ----------
__device__ float g_rt [BB*HIDD];
__device__ float g_xc [BB*PP];
__device__ float g_q  [BB*HIDD];
__device__ float g_k  [BB*HIDD];
__device__ float g_v  [BB*HIDD];
__device__ float g_o  [BB*HIDD];
__device__ float g_sk [BB*HIDD];

// fp16 operands (16B-aligned for cp.async)
#define WTOT 14680064
__device__ __align__(256) __half g_wf[WTOT];                 // weights fp16
__device__ __align__(256) __half g_xnh[BB*DD];
__device__ __align__(256) __half g_xth[BB*PP];
__device__ __align__(256) __half g_xch[BB*PP];
__device__ __align__(256) __half g_yh [BB*HIDD];

// weight offsets (elements) in g_wf
#define OFF_UPL  0u
#define OFF_UPR  2097152u
#define OFF_Q    3145728u
#define OFF_K    5242880u
#define OFF_V    7340032u
#define OFF_O    9437184u
#define OFF_SKIP 11534336u
#define OFF_DOWN 13631488u

// ---------------- PTX helpers ----------------------------------------------
__device__ __forceinline__ uint32_t smem_u32(const void* p) {
    uint32_t a;
    asm("{ .reg .u64 t; cvta.to.shared.u64 t, %1; cvt.u32.u64 %0, t; }" : "=r"(a) : "l"(p));
    return a;
}
__device__ __forceinline__ void cp16(uint32_t dst, const void* src) {
    asm volatile("cp.async.cg.shared.global [%0], [%1], 16;" :: "r"(dst), "l"(src));
}
#define CP_COMMIT() asm volatile("cp.async.commit_group;" ::: "memory")
#define CP_WAIT2()  asm volatile("cp.async.wait_group 2;" ::: "memory")
#define CP_WAIT1()  asm volatile("cp.async.wait_group 1;" ::: "memory")
#define CP_WAIT0()  asm volatile("cp.async.wait_group 0;" ::: "memory")

__device__ __forceinline__ void ldsm4(uint32_t* r, uint32_t addr) {
    asm volatile("ldmatrix.sync.aligned.m8n8.x4.shared.b16 {%0,%1,%2,%3}, [%4];"
                 : "=r"(r[0]), "=r"(r[1]), "=r"(r[2]), "=r"(r[3]) : "r"(addr));
}
__device__ __forceinline__ void mma16816(float* c, const uint32_t* a, uint32_t b0, uint32_t b1) {
    asm volatile(
        "mma.sync.aligned.m16n8k16.row.col.f32.f16.f16.f32 "
        "{%0,%1,%2,%3}, {%4,%5,%6,%7}, {%8,%9}, {%0,%1,%2,%3};"
        : "+f"(c[0]), "+f"(c[1]), "+f"(c[2]), "+f"(c[3])
        : "r"(a[0]), "r"(a[1]), "r"(a[2]), "r"(a[3]), "r"(b0), "r"(b1));
}

// chunk-XOR swizzle: 64B rows, 4 chunks of 16B, conflict-free for ldmatrix
__device__ __forceinline__ uint32_t swz(int r, int c) {
    return (uint32_t)(r * 64 + ((c ^ ((r >> 1) & 3)) * 16));
}

// ---------------- tensor GEMM (mma.sync fp16) --------------------------------
struct TSeg {
    const __half *X;   // [M, K] fp16 activations
    const __half *W;   // [N, K] fp16 weights
    const float* bias;
    const float* resid;
    float* Y;          // fp32 out (nullable)
    __half *Yh;        // optional fp16 out (nullable)
    float scale;
    int act;      // 1 = sigmoid
    int nblk;     // N / TBN
    int N;
};
struct TArgs { TSeg s[5]; int nseg; int K; };

__device__ __forceinline__ void load_stage(uint32_t sb,
        const __half* ax, const __half* bw,
        int K, int kbase, int tid) {
    // A: 16 rows x 4 chunks = 64 chunk loads (threads 0-63)
    if (tid < 64) {
        int row = tid >> 2, c = tid & 3;
        uint32_t o = swz(row, c);
        const size_t g = (size_t)row * K + kbase + c * 8;
        cp16(sb + SOFF_A + o, ax + g);
    }
    // B: 128 rows x 4 chunks = 512 chunk loads (4 per thread)
#pragma unroll
    for (int i = 0; i < 4; i++) {
        int idx = tid + 128 * i;
        int row = idx >> 2, c = idx & 3;
        uint32_t o = swz(row, c);
        const size_t g = (size_t)row * K + kbase + c * 8;
        cp16(sb + SOFF_B + o, bw + g);
    }
}

__global__ __launch_bounds__(128)
void tgemm(TArgs args) {
    extern __shared__ char dyn[];
    uint32_t sb = smem_u32(dyn);
    sb = (sb + 127) & ~127u;

    int nb = blockIdx.x, si = 0;
    while (si < args.nseg - 1 && nb >= args.s[si].nblk) { nb -= args.s[si].nblk; si++; }
    const TSeg sg = args.s[si];
    const int K = args.K;
    const int bm = blockIdx.y;

    int tid = threadIdx.x;
    int wn = tid >> 5, lane = tid & 31;   // 4 warps along N (32 each)

    const __half* ax = sg.X + (size_t)bm * TBM * K;
    const __half* bw = sg.W + (size_t)nb * TBN * K;

    float acc[4][4];
#pragma unroll
    for (int j = 0; j < 4; j++)
#pragma unroll
        for (int l = 0; l < 4; l++) acc[j][l] = 0.f;

    const int T = K / TBK;

    load_stage(sb, ax, bw, K, 0, tid);
    CP_COMMIT();
    load_stage(sb + STAGE_B, ax, bw, K, TBK, tid);
    CP_COMMIT();

    int lr = lane & 15, lch = lane >> 4;

    for (int t = 0; t < T; t++) {
        uint32_t cur = sb + (t & 3) * STAGE_B;
        if (t + 2 < T) {
            load_stage(sb + ((t + 2) & 3) * STAGE_B, ax, bw, K, (t + 2) * TBK, tid);
            CP_COMMIT();
            CP_WAIT2();
        } else if (t + 1 < T) {
            CP_WAIT1();
        } else {
            CP_WAIT0();
        }
        __syncthreads();
        // single barrier: write stage (t+2)&3 is distance 3 (mod 4) from the
        // slowest possible reader stage (t-1)&3 — never collides.

#pragma unroll
        for (int kk = 0; kk < 2; kk++) {
            int c = kk * 2 + lch;
            uint32_t Af[4];
            {
                uint32_t o = swz(lr, c);
                ldsm4(Af, cur + SOFF_A + o);
            }
            uint32_t Bf[2][4];
#pragma unroll
            for (int jn = 0; jn < 2; jn++) {
                int r = wn * 32 + jn * 16 + lr;
                uint32_t o = swz(r, c);
                ldsm4(Bf[jn], cur + SOFF_B + o);
            }
#pragma unroll
            for (int inn = 0; inn < 4; inn++) {
                int jn = inn >> 1, hb = inn & 1;
                mma16816(acc[inn], Af, Bf[jn][hb], Bf[jn][hb + 2]);
            }
        }
    }

    int group = lane >> 2, tig = lane & 3;
#pragma unroll
    for (int inn = 0; inn < 4; inn++) {
        int mrow = bm * TBM + group;
        int col  = nb * TBN + wn * 32 + inn * 8 + tig * 2;
#pragma unroll
        for (int half = 0; half < 2; half++) {
            int row = mrow + half * 8;
            float2 v;
            v.x = acc[inn][half * 2 + 0];
            v.y = acc[inn][half * 2 + 1];
            if (sg.bias) { v.x += sg.bias[col]; v.y += sg.bias[col + 1]; }
            v.x *= sg.scale; v.y *= sg.scale;
            if (sg.act == 1) {
                v.x = 1.f / (1.f + expf(-v.x));
                v.y = 1.f / (1.f + expf(-v.y));
            }
            if (sg.resid) {
                const float2 rv = *(const float2*)&sg.resid[(size_t)row * sg.N + col];
                v.x += rv.x; v.y += rv.y;
            }
            size_t off = (size_t)row * sg.N + col;
            if (sg.Y) *(float2*)&sg.Y[off] = v;
            if (sg.Yh)
                *(__half2*)&sg.Yh[off] = __half2(__float2half(v.x), __float2half(v.y));
        }
    }
}

// ---------------- fp32 -> fp16 weight convert --------------------------------
struct SSeg { const float* src; __half* dst; int nblk; };
struct SArgs { SSeg s[8]; int nseg; };

__global__ void split_kernel(SArgs a) {
    int b = blockIdx.x, si = 0;
    while (si < a.nseg - 1 && b >= a.s[si].nblk) { b -= a.s[si].nblk; si++; }
    const SSeg sg = a.s[si];
    int i = b * 256 + threadIdx.x;          // index of float4
    float4 v = ((const float4*)sg.src)[i];
    __half2* pd = (__half2*)(sg.dst + (size_t)i * 4);
    pd[0] = __half2(__float2half(v.x), __float2half(v.y));
    pd[1] = __half2(__float2half(v.z), __float2half(v.w));
}

// ---------------- LayerNorm (emits fp16 directly) ----------------------------
__global__ void ln_kernel(const float* __restrict__ x,
                          const float* __restrict__ w,
                          const float* __restrict__ b) {
    int row = blockIdx.x;
    const float* xr = x + row * DD;
    float s = 0.f, s2 = 0.f;
    for (int i = threadIdx.x; i < DD; i += blockDim.x) {
        float v = xr[i]; s += v; s2 += v * v;
    }
    __shared__ float rs[32], rs2[32];
    for (int o = 16; o; o >>= 1) {
        s  += __shfl_xor_sync(0xffffffffu, s,  o);
        s2 += __shfl_xor_sync(0xffffffffu, s2, o);
    }
    int wr = threadIdx.x >> 5, ln = threadIdx.x & 31;
    if (ln == 0) { rs[wr] = s; rs2[wr] = s2; }
    __syncthreads();
    if (wr == 0) {
        int nw = blockDim.x >> 5;
        s  = (ln < nw) ? rs[ln]  : 0.f;
        s2 = (ln < nw) ? rs2[ln] : 0.f;
        for (int o = 16; o; o >>= 1) {
            s  += __shfl_xor_sync(0xffffffffu, s,  o);
            s2 += __shfl_xor_sync(0xffffffffu, s2, o);
        }
        if (ln == 0) { rs[0] = s; rs2[0] = s2; }
    }
    __syncthreads();
    float mu  = rs[0] / (float)DD;
    float var = rs2[0] / (float)DD - mu * mu;
    float r   = rsqrtf(var + EPSF);
    for (int i = threadIdx.x; i < DD; i += blockDim.x) {
        float v = (xr[i] - mu) * r * w[i] + b[i];
        g_xnh[row * DD + i] = __float2half(v);
    }
}

// ---------------- causal conv (K=4) + SiLU (reads xth) -----------------------
__global__ void conv_kernel(const float* __restrict__ cw,
                            const float* __restrict__ cb) {
    int idx = blockIdx.x * blockDim.x + threadIdx.x;
    int b = idx / PP, p = idx % PP;
    const __half* xh = g_xth + (size_t)b * PP;
    float s = *cb;
#pragma unroll
    for (int j = 0; j < KW; j++) {
        int src = p + j - (KW - 1);
        if (src >= 0)
            s += cw[j] * __half2float(xh[src]);
    }
    float v = s / (1.f + expf(-s));
    g_xc[idx] = v;
    g_xch[idx] = __float2half(v);
}

// ---- cell: i/f gates, c_t, n_t, num/den, o-gate, GroupNorm, mix (fused) ----
__global__ void cell_kernel(const float* __restrict__ c_in,
                            const float* __restrict__ n_in,
                            const float* __restrict__ m_in,
                            const float* __restrict__ gnw,
                            const float* __restrict__ gnb,
                            const float* __restrict__ Wi, const float* __restrict__ bi,
                            const float* __restrict__ Wf, const float* __restrict__ bf,
                            float* __restrict__ c_out,
                            float* __restrict__ n_out,
                            float* __restrict__ m_out) {
    int bh = blockIdx.x;
    int b = bh >> 3, h = bh & 7;
    __shared__ float sq[HDIM], sk[HDIM], sv[HDIM], sh[HDIM];
    __shared__ float s_red[16];
    __shared__ float s_ig, s_fg, s_den, s_mu, s_rstd;
    int tid = threadIdx.x;
    int warp = tid >> 5, lane = tid & 31;

    if (tid < HDIM) {
        int off = b * HIDD + h * HDIM + tid;
        sq[tid] = g_q[off]; sk[tid] = g_k[off]; sv[tid] = g_v[off];
    }

    // fused i/f dot products over PP (exact fp32)
    {
        const float* xc = g_xc + (size_t)b * PP;
        const float* wi = Wi + (size_t)h * PP;
        const float* wf = Wf + (size_t)h * PP;
        float pi = 0.f, pf = 0.f;
#pragma unroll
        for (int j = tid; j < PP; j += 256) {
            float x = xc[j];
            pi += x * wi[j];
            pf += x * wf[j];
        }
        for (int o = 16; o; o >>= 1) {
            pi += __shfl_xor_sync(0xffffffffu, pi, o);
            pf += __shfl_xor_sync(0xffffffffu, pf, o);
        }
        if (lane == 0) { s_red[warp] = pi; s_red[8 + warp] = pf; }
    }
    __syncthreads();
    if (tid == 0) {
        float it = s_red[0]+s_red[1]+s_red[2]+s_red[3]+s_red[4]+s_red[5]+s_red[6]+s_red[7] + bi[h];
        float ft = s_red[8]+s_red[9]+s_red[10]+s_red[11]+s_red[12]+s_red[13]+s_red[14]+s_red[15] + bf[h];
        float m0 = m_in[bh];
        float mt = fmaxf(ft + m0, it);
        s_ig = expf(it - mt);
        s_fg = expf(ft - mt + m0);
        m_out[bh] = mt;
    }
    __syncthreads();
    float ig = s_ig, fg = s_fg;

    float dp = 0.f;
    if (tid < HDIM) {
        float nt = fg * n_in[(size_t)bh * HDIM + tid] + ig * sk[tid];
        n_out[(size_t)bh * HDIM + tid] = nt;
        dp = nt * sq[tid];
    }
    for (int o = 16; o; o >>= 1) dp += __shfl_xor_sync(0xffffffffu, dp, o);
    if (lane == 0) s_red[warp] = dp;
    __syncthreads();
    if (tid == 0)
        s_den = fmaxf(s_red[0] + s_red[1] + s_red[2] + s_red[3], 1.0f);

    float4 kv = ((const float4*)sk)[lane];
    float4 qv = ((const float4*)sq)[lane];
    size_t base = (size_t)bh * HDIM * HDIM;
#pragma unroll
    for (int it2 = 0; it2 < 8; it2++) {
        int d0 = warp + it2 * 16;
        int d1 = d0 + 8;
        const float4* s0 = (const float4*)(c_in + base + (size_t)d0 * HDIM);
        const float4* s1 = (const float4*)(c_in + base + (size_t)d1 * HDIM);
        float4*       t0 = (float4*)(c_out + base + (size_t)d0 * HDIM);
        float4*       t1 = (float4*)(c_out + base + (size_t)d1 * HDIM);
        float i0 = ig * sv[d0], i1 = ig * sv[d1];
        float4 c0 = s0[lane], c1 = s1[lane];
        float4 n0, n1;
        n0.x = fg * c0.x + i0 * kv.x; n1.x = fg * c1.x + i1 * kv.x;
        n0.y = fg * c0.y + i0 * kv.y; n1.y = fg * c1.y + i1 * kv.y;
        n0.z = fg * c0.z + i0 * kv.z; n1.z = fg * c1.z + i1 * kv.z;
        n0.w = fg * c0.w + i0 * kv.w; n1.w = fg * c1.w + i1 * kv.w;
        t0[lane] = n0; t1[lane] = n1;
        float a0 = n0.x * qv.x + n0.y * qv.y + n0.z * qv.z + n0.w * qv.w;
        float a1 = n1.x * qv.x + n1.y * qv.y + n1.z * qv.z + n1.w * qv.w;
        for (int o = 16; o; o >>= 1) {
            a0 += __shfl_xor_sync(0xffffffffu, a0, o);
            a1 += __shfl_xor_sync(0xffffffffu, a1, o);
        }
        if (lane == 0) { sh[d0] = a0; sh[d1] = a1; }
    }
    __syncthreads();

    float hv = 0.f;
    if (tid < HDIM)
        hv = g_o[b * HIDD + h * HDIM + tid] * sh[tid] / s_den;
    float s1 = hv, s2 = hv * hv;
    for (int o = 16; o; o >>= 1) {
        s1 += __shfl_xor_sync(0xffffffffu, s1, o);
        s2 += __shfl_xor_sync(0xffffffffu, s2, o);
    }
    if (lane == 0) { s_red[warp] = s1; s_red[8 + warp] = s2; }
    __syncthreads();
    if (tid == 0) {
        float m1 = (s_red[0] + s_red[1] + s_red[2] + s_red[3]) / (float)HDIM;
        float m2 = (s_red[8] + s_red[9] + s_red[10] + s_red[11]) / (float)HDIM;
        s_mu = m1;
        s_rstd = rsqrtf(m2 - m1 * m1 + EPSF);
    }
    __syncthreads();
    if (tid < HDIM) {
        int c = h * HDIM + tid;
        int gi = b * HIDD + c;
        float hn = (hv - s_mu) * s_rstd * gnw[c] + gnb[c];
        float r = g_rt[gi];
        float y = (hn + g_sk[gi]) * (r / (1.f + expf(-r)));
        g_yh[gi] = __float2half(y);
    }
}

// ---------------- host ---------------------------------------------------------
static void* sym_addr(const void* sym) {
    void* p = nullptr;
    cudaGetSymbolAddress(&p, sym);
    return p;
}

extern "C" void kernel_launch(void* const* d_in, const int* in_sizes, int n_in,
                              void* d_out, int out_size) {
    const float* seq    = (const float*)d_in[0];
    const float* c_tm1  = (const float*)d_in[1];
    const float* n_tm1  = (const float*)d_in[2];
    const float* m_tm1  = (const float*)d_in[3];
    const float* ln_w   = (const float*)d_in[4];
    const float* ln_b   = (const float*)d_in[5];
    const float* gn_w   = (const float*)d_in[6];
    const float* gn_b   = (const float*)d_in[7];
    const float* up_l_w = (const float*)d_in[8];
    const float* up_l_b = (const float*)d_in[9];
    const float* up_r_w = (const float*)d_in[10];
    const float* up_r_b = (const float*)d_in[11];
    const float* down_w = (const float*)d_in[12];
    const float* down_b = (const float*)d_in[13];
    const float* Wi_w   = (const float*)d_in[14];
    const float* Wi_b   = (const float*)d_in[15];
    const float* Wf_w   = (const float*)d_in[16];
    const float* Wf_b   = (const float*)d_in[17];
    const float* Wo_w   = (const float*)d_in[18];
    const float* Wo_b   = (const float*)d_in[19];
    const float* Wq_w   = (const float*)d_in[20];
    const float* Wq_b   = (const float*)d_in[21];
    const float* Wk_w   = (const float*)d_in[22];
    const float* Wk_b   = (const float*)d_in[23];
    const float* Wv_w   = (const float*)d_in[24];
    const float* Wv_b   = (const float*)d_in[25];
    const float* conv_w = (const float*)d_in[26];
    const float* conv_b = (const float*)d_in[27];
    const float* skip_w = (const float*)d_in[28];

    float* out   = (float*)d_out;
    float* c_out = out + (size_t)BB * DD;
    float* n_out = c_out + (size_t)BB * HH * HDIM * HDIM;
    float* m_out = n_out + (size_t)BB * HH * HDIM;

    float* p_rt = (float*)sym_addr(g_rt);
    float* p_q  = (float*)sym_addr(g_q);
    float* p_k  = (float*)sym_addr(g_k);
    float* p_v  = (float*)sym_addr(g_v);
    float* p_o  = (float*)sym_addr(g_o);
    float* p_sk = (float*)sym_addr(g_sk);

    __half* wf  = (__half*)sym_addr(g_wf);
    __half* xnh = (__half*)sym_addr(g_xnh);
    __half* xth = (__half*)sym_addr(g_xth);
    __half* xch = (__half*)sym_addr(g_xch);
    __half* yh  = (__half*)sym_addr(g_yh);

    cudaFuncSetAttribute(tgemm, cudaFuncAttributeMaxDynamicSharedMemorySize, DYN_SMEM);

    // side stream + events for overlapping the weight conversion (created once;
    // the launched work is identical on every call)
    static cudaStream_t s2 = nullptr;
    static cudaEvent_t eFork = nullptr, e1 = nullptr, e2 = nullptr;
    if (s2 == nullptr) {
        cudaStreamCreateWithFlags(&s2, cudaStreamNonBlocking);
        cudaEventCreateWithFlags(&eFork, cudaEventDisableTiming);
        cudaEventCreateWithFlags(&e1, cudaEventDisableTiming);
        cudaEventCreateWithFlags(&e2, cudaEventDisableTiming);
    }

    const float kscale = 1.0f / sqrtf((float)HDIM);

    // fork side stream from main
    cudaEventRecord(eFork, 0);
    cudaStreamWaitEvent(s2, eFork, 0);

    // side stream: convert up_l/up_r weights first (needed by stage1), then the rest
    {
        SArgs a; a.nseg = 2;
        a.s[0] = { up_l_w, wf + OFF_UPL, 2048 };
        a.s[1] = { up_r_w, wf + OFF_UPR, 1024 };
        split_kernel<<<3072, 256, 0, s2>>>(a);
        cudaEventRecord(e1, s2);
    }
    {
        SArgs a; a.nseg = 6;
        a.s[0] = { Wq_w,   wf + OFF_Q,    2048 };
        a.s[1] = { Wk_w,   wf + OFF_K,    2048 };
        a.s[2] = { Wv_w,   wf + OFF_V,    2048 };
        a.s[3] = { Wo_w,   wf + OFF_O,    2048 };
        a.s[4] = { skip_w, wf + OFF_SKIP, 2048 };
        a.s[5] = { down_w, wf + OFF_DOWN, 1024 };
        split_kernel<<<11264, 256, 0, s2>>>(a);
        cudaEventRecord(e2, s2);
    }

    // main stream: LayerNorm -> xnh (overlaps split #1)
    ln_kernel<<<BB, 256>>>(seq, ln_w, ln_b);

    // stage1 needs up_l/up_r weights
    cudaStreamWaitEvent(0, e1, 0);
    {
        TArgs a; a.nseg = 2; a.K = DD;
        a.s[0] = { xnh, wf + OFF_UPL, up_l_b, nullptr, nullptr, xth, 1.f, 0, PP / TBN,   PP   };
        a.s[1] = { xnh, wf + OFF_UPR, up_r_b, nullptr, p_rt, nullptr, 1.f, 0, HIDD / TBN, HIDD };
        tgemm<<<dim3(PP / TBN + HIDD / TBN, BB / TBM), 128, DYN_SMEM>>>(a);
    }

    // causal conv + SiLU -> xc fp32 + xch (overlaps split #2)
    conv_kernel<<<(BB * PP) / 256, 256>>>(conv_w, conv_b);

    // stage2 needs the remaining weights
    cudaStreamWaitEvent(0, e2, 0);
    {
        TArgs a; a.nseg = 5; a.K = PP;
        a.s[0] = { xch, wf + OFF_Q,    Wq_b,    nullptr, p_q,  nullptr, 1.f,    0, HIDD / TBN, HIDD };
        a.s[1] = { xch, wf + OFF_K,    Wk_b,    nullptr, p_k,  nullptr, kscale, 0, HIDD / TBN, HIDD };
        a.s[2] = { xth, wf + OFF_V,    Wv_b,    nullptr, p_v,  nullptr, 1.f,    0, HIDD / TBN, HIDD };
        a.s[3] = { xth, wf + OFF_O,    Wo_b,    nullptr, p_o,  nullptr, 1.f,    1, HIDD / TBN, HIDD };
        a.s[4] = { xch, wf + OFF_SKIP, nullptr, nullptr, p_sk, nullptr, 1.f,    0, HIDD / TBN, HIDD };
        tgemm<<<dim3(5 * (HIDD / TBN), BB / TBM), 128, DYN_SMEM>>>(a);
    }

    // cell update (+i/f gates, +groupnorm, +mix) -> yh
    cell_kernel<<<BB * HH, 256>>>(c_tm1, n_tm1, m_tm1, gn_w, gn_b,
                                  Wi_w, Wi_b, Wf_w, Wf_b,
                                  c_out, n_out, m_out);

    // down projection + bias + residual
    {
        TArgs a; a.nseg = 1; a.K = HIDD;
        a.s[0] = { yh, wf + OFF_DOWN, down_b, seq, out, nullptr, 1.f, 0, DD / TBN, DD };
        tgemm<<<dim3(DD / TBN, BB / TBM), 128, DYN_SMEM>>>(a);
    }
}

// round 15
// speedup vs baseline: 1.1725x; 1.0449x over previous
#include <cuda_runtime.h>
#include <cuda_fp16.h>
#include <cstdint>
#include <math.h>

#define BB   256
#define DD   1024
#define HH   8
#define HDIM 128
#define PP   2048
#define HIDD 1024
#define KW   4
#define EPSF 1e-5f

// mma.sync GEMM tiling: CTA 16x128, 4 warps (1m x 4n), warp tile 16x32
#define TBM  16
#define TBN  128
#define TBK  32
#define SOFF_A  0
#define SOFF_B  1024
#define STAGE_B 9216
#define NSTAGE  4
#define DYN_SMEM (NSTAGE*STAGE_B + 128)

// ---------------- scratch (device globals; no allocation allowed) ----------
__device__ float g_rt [BB*HIDD];
__device__ float g_xc [BB*PP];
__device__ float g_q  [BB*HIDD];
__device__ float g_k  [BB*HIDD];
__device__ float g_v  [BB*HIDD];
__device__ float g_o  [BB*HIDD];
__device__ float g_sk [BB*HIDD];

// fp16 operands (16B-aligned for cp.async)
#define WTOT 14680064
__device__ __align__(256) __half g_wf[WTOT];                 // weights fp16
__device__ __align__(256) __half g_xnh[BB*DD];
__device__ __align__(256) __half g_xth[BB*PP];
__device__ __align__(256) __half g_xch[BB*PP];
__device__ __align__(256) __half g_yh [BB*HIDD];

// weight offsets (elements) in g_wf
#define OFF_UPL  0u
#define OFF_UPR  2097152u
#define OFF_Q    3145728u
#define OFF_K    5242880u
#define OFF_V    7340032u
#define OFF_O    9437184u
#define OFF_SKIP 11534336u
#define OFF_DOWN 13631488u

// ---------------- PTX helpers ----------------------------------------------
__device__ __forceinline__ uint32_t smem_u32(const void* p) {
    uint32_t a;
    asm("{ .reg .u64 t; cvta.to.shared.u64 t, %1; cvt.u32.u64 %0, t; }" : "=r"(a) : "l"(p));
    return a;
}
__device__ __forceinline__ void cp16(uint32_t dst, const void* src) {
    asm volatile("cp.async.cg.shared.global [%0], [%1], 16;" :: "r"(dst), "l"(src));
}
#define CP_COMMIT() asm volatile("cp.async.commit_group;" ::: "memory")
#define CP_WAIT2()  asm volatile("cp.async.wait_group 2;" ::: "memory")
#define CP_WAIT1()  asm volatile("cp.async.wait_group 1;" ::: "memory")
#define CP_WAIT0()  asm volatile("cp.async.wait_group 0;" ::: "memory")

__device__ __forceinline__ void ldsm4(uint32_t* r, uint32_t addr) {
    asm volatile("ldmatrix.sync.aligned.m8n8.x4.shared.b16 {%0,%1,%2,%3}, [%4];"
                 : "=r"(r[0]), "=r"(r[1]), "=r"(r[2]), "=r"(r[3]) : "r"(addr));
}
__device__ __forceinline__ void mma16816(float* c, const uint32_t* a, uint32_t b0, uint32_t b1) {
    asm volatile(
        "mma.sync.aligned.m16n8k16.row.col.f32.f16.f16.f32 "
        "{%0,%1,%2,%3}, {%4,%5,%6,%7}, {%8,%9}, {%0,%1,%2,%3};"
        : "+f"(c[0]), "+f"(c[1]), "+f"(c[2]), "+f"(c[3])
        : "r"(a[0]), "r"(a[1]), "r"(a[2]), "r"(a[3]), "r"(b0), "r"(b1));
}

// chunk-XOR swizzle: 64B rows, 4 chunks of 16B, conflict-free for ldmatrix
__device__ __forceinline__ uint32_t swz(int r, int c) {
    return (uint32_t)(r * 64 + ((c ^ ((r >> 1) & 3)) * 16));
}

// ---------------- tensor GEMM (mma.sync fp16) --------------------------------
struct TSeg {
    const __half *X;   // [M, K] fp16 activations
    const __half *W;   // [N, K] fp16 weights
    const float* bias;
    const float* resid;
    float* Y;          // fp32 out (nullable)
    __half *Yh;        // optional fp16 out (nullable)
    float scale;
    int act;      // 1 = sigmoid
    int nblk;     // N / TBN
    int N;
};
struct TArgs { TSeg s[5]; int nseg; int K; };

__device__ __forceinline__ void load_stage(uint32_t sb,
        const __half* ax, const __half* bw,
        int K, int kbase, int tid) {
    if (tid < 64) {
        int row = tid >> 2, c = tid & 3;
        uint32_t o = swz(row, c);
        const size_t g = (size_t)row * K + kbase + c * 8;
        cp16(sb + SOFF_A + o, ax + g);
    }
#pragma unroll
    for (int i = 0; i < 4; i++) {
        int idx = tid + 128 * i;
        int row = idx >> 2, c = idx & 3;
        uint32_t o = swz(row, c);
        const size_t g = (size_t)row * K + kbase + c * 8;
        cp16(sb + SOFF_B + o, bw + g);
    }
}

__global__ __launch_bounds__(128)
void tgemm(TArgs args) {
    extern __shared__ char dyn[];
    uint32_t sb = smem_u32(dyn);
    sb = (sb + 127) & ~127u;

    int nb = blockIdx.x, si = 0;
    while (si < args.nseg - 1 && nb >= args.s[si].nblk) { nb -= args.s[si].nblk; si++; }
    const TSeg sg = args.s[si];
    const int K = args.K;
    const int bm = blockIdx.y;

    int tid = threadIdx.x;
    int wn = tid >> 5, lane = tid & 31;

    const __half* ax = sg.X + (size_t)bm * TBM * K;
    const __half* bw = sg.W + (size_t)nb * TBN * K;

    float acc[4][4];
#pragma unroll
    for (int j = 0; j < 4; j++)
#pragma unroll
        for (int l = 0; l < 4; l++) acc[j][l] = 0.f;

    const int T = K / TBK;

    load_stage(sb, ax, bw, K, 0, tid);
    CP_COMMIT();
    load_stage(sb + STAGE_B, ax, bw, K, TBK, tid);
    CP_COMMIT();

    int lr = lane & 15, lch = lane >> 4;

    for (int t = 0; t < T; t++) {
        uint32_t cur = sb + (t & 3) * STAGE_B;
        if (t + 2 < T) {
            load_stage(sb + ((t + 2) & 3) * STAGE_B, ax, bw, K, (t + 2) * TBK, tid);
            CP_COMMIT();
            CP_WAIT2();
        } else if (t + 1 < T) {
            CP_WAIT1();
        } else {
            CP_WAIT0();
        }
        __syncthreads();

#pragma unroll
        for (int kk = 0; kk < 2; kk++) {
            int c = kk * 2 + lch;
            uint32_t Af[4];
            {
                uint32_t o = swz(lr, c);
                ldsm4(Af, cur + SOFF_A + o);
            }
            uint32_t Bf[2][4];
#pragma unroll
            for (int jn = 0; jn < 2; jn++) {
                int r = wn * 32 + jn * 16 + lr;
                uint32_t o = swz(r, c);
                ldsm4(Bf[jn], cur + SOFF_B + o);
            }
#pragma unroll
            for (int inn = 0; inn < 4; inn++) {
                int jn = inn >> 1, hb = inn & 1;
                mma16816(acc[inn], Af, Bf[jn][hb], Bf[jn][hb + 2]);
            }
        }
    }

    int group = lane >> 2, tig = lane & 3;
#pragma unroll
    for (int inn = 0; inn < 4; inn++) {
        int mrow = bm * TBM + group;
        int col  = nb * TBN + wn * 32 + inn * 8 + tig * 2;
#pragma unroll
        for (int half = 0; half < 2; half++) {
            int row = mrow + half * 8;
            float2 v;
            v.x = acc[inn][half * 2 + 0];
            v.y = acc[inn][half * 2 + 1];
            if (sg.bias) { v.x += sg.bias[col]; v.y += sg.bias[col + 1]; }
            v.x *= sg.scale; v.y *= sg.scale;
            if (sg.act == 1) {
                v.x = 1.f / (1.f + expf(-v.x));
                v.y = 1.f / (1.f + expf(-v.y));
            }
            if (sg.resid) {
                const float2 rv = *(const float2*)&sg.resid[(size_t)row * sg.N + col];
                v.x += rv.x; v.y += rv.y;
            }
            size_t off = (size_t)row * sg.N + col;
            if (sg.Y) *(float2*)&sg.Y[off] = v;
            if (sg.Yh)
                *(__half2*)&sg.Yh[off] = __half2(__float2half(v.x), __float2half(v.y));
        }
    }
}

// ---------------- fp32 -> fp16 weight convert --------------------------------
struct SSeg { const float* src; __half* dst; int nblk; };
struct SArgs { SSeg s[8]; int nseg; };

__global__ void split_kernel(SArgs a) {
    int b = blockIdx.x, si = 0;
    while (si < a.nseg - 1 && b >= a.s[si].nblk) { b -= a.s[si].nblk; si++; }
    const SSeg sg = a.s[si];
    int i = b * 256 + threadIdx.x;
    float4 v = ((const float4*)sg.src)[i];
    __half2* pd = (__half2*)(sg.dst + (size_t)i * 4);
    pd[0] = __half2(__float2half(v.x), __float2half(v.y));
    pd[1] = __half2(__float2half(v.z), __float2half(v.w));
}

// ---------------- LayerNorm (emits fp16 directly) ----------------------------
__global__ void ln_kernel(const float* __restrict__ x,
                          const float* __restrict__ w,
                          const float* __restrict__ b) {
    int row = blockIdx.x;
    const float* xr = x + row * DD;
    float s = 0.f, s2 = 0.f;
    for (int i = threadIdx.x; i < DD; i += blockDim.x) {
        float v = xr[i]; s += v; s2 += v * v;
    }
    __shared__ float rs[32], rs2[32];
    for (int o = 16; o; o >>= 1) {
        s  += __shfl_xor_sync(0xffffffffu, s,  o);
        s2 += __shfl_xor_sync(0xffffffffu, s2, o);
    }
    int wr = threadIdx.x >> 5, ln = threadIdx.x & 31;
    if (ln == 0) { rs[wr] = s; rs2[wr] = s2; }
    __syncthreads();
    if (wr == 0) {
        int nw = blockDim.x >> 5;
        s  = (ln < nw) ? rs[ln]  : 0.f;
        s2 = (ln < nw) ? rs2[ln] : 0.f;
        for (int o = 16; o; o >>= 1) {
            s  += __shfl_xor_sync(0xffffffffu, s,  o);
            s2 += __shfl_xor_sync(0xffffffffu, s2, o);
        }
        if (ln == 0) { rs[0] = s; rs2[0] = s2; }
    }
    __syncthreads();
    float mu  = rs[0] / (float)DD;
    float var = rs2[0] / (float)DD - mu * mu;
    float r   = rsqrtf(var + EPSF);
    for (int i = threadIdx.x; i < DD; i += blockDim.x) {
        float v = (xr[i] - mu) * r * w[i] + b[i];
        g_xnh[row * DD + i] = __float2half(v);
    }
}

// ---------------- causal conv (K=4) + SiLU — 8 outputs/thread ----------------
__global__ void conv_kernel(const float* __restrict__ cw,
                            const float* __restrict__ cb) {
    int idx8 = blockIdx.x * blockDim.x + threadIdx.x;   // over BB*PP/8
    int b = idx8 / (PP / 8);
    int p0 = (idx8 % (PP / 8)) * 8;
    const __half* xrow = g_xth + (size_t)b * PP;

    // current 8 halfs + previous 8 halfs (for 3-left halo)
    __half cu[8], pv[8];
    *(int4*)cu = *(const int4*)(xrow + p0);
    if (p0 > 0) *(int4*)pv = *(const int4*)(xrow + p0 - 8);
    else {
#pragma unroll
        for (int j = 0; j < 8; j++) pv[j] = __float2half(0.f);
    }

    float xx[11];
#pragma unroll
    for (int j = 0; j < 3; j++) xx[j] = __half2float(pv[5 + j]);
#pragma unroll
    for (int j = 0; j < 8; j++) xx[3 + j] = __half2float(cu[j]);

    float w0 = cw[0], w1 = cw[1], w2 = cw[2], w3 = cw[3], bb = *cb;
    float out[8];
#pragma unroll
    for (int j = 0; j < 8; j++) {
        float s = bb + w0 * xx[j] + w1 * xx[j + 1] + w2 * xx[j + 2] + w3 * xx[j + 3];
        out[j] = s / (1.f + expf(-s));
    }

    float* xcrow = g_xc + (size_t)b * PP + p0;
    *(float4*)xcrow       = make_float4(out[0], out[1], out[2], out[3]);
    *(float4*)(xcrow + 4) = make_float4(out[4], out[5], out[6], out[7]);
    __half2 hc[4];
#pragma unroll
    for (int j = 0; j < 4; j++)
        hc[j] = __half2(__float2half(out[2 * j]), __float2half(out[2 * j + 1]));
    *(int4*)(g_xch + (size_t)b * PP + p0) = *(int4*)hc;
}

// ---- cell: i/f gates, c_t, n_t, num/den, o-gate, GroupNorm, mix (fused) ----
__global__ void cell_kernel(const float* __restrict__ c_in,
                            const float* __restrict__ n_in,
                            const float* __restrict__ m_in,
                            const float* __restrict__ gnw,
                            const float* __restrict__ gnb,
                            const float* __restrict__ Wi, const float* __restrict__ bi,
                            const float* __restrict__ Wf, const float* __restrict__ bf,
                            float* __restrict__ c_out,
                            float* __restrict__ n_out,
                            float* __restrict__ m_out) {
    int bh = blockIdx.x;
    int b = bh >> 3, h = bh & 7;
    __shared__ float sq[HDIM], sk[HDIM], sv[HDIM], sh[HDIM];
    __shared__ float s_red[16];
    __shared__ float s_ig, s_fg, s_den, s_mu, s_rstd;
    int tid = threadIdx.x;
    int warp = tid >> 5, lane = tid & 31;

    if (tid < HDIM) {
        int off = b * HIDD + h * HDIM + tid;
        sq[tid] = g_q[off]; sk[tid] = g_k[off]; sv[tid] = g_v[off];
    }

    // fused i/f dot products over PP (exact fp32)
    {
        const float* xc = g_xc + (size_t)b * PP;
        const float* wi = Wi + (size_t)h * PP;
        const float* wf = Wf + (size_t)h * PP;
        float pi = 0.f, pf = 0.f;
#pragma unroll
        for (int j = tid; j < PP; j += 256) {
            float x = xc[j];
            pi += x * wi[j];
            pf += x * wf[j];
        }
        for (int o = 16; o; o >>= 1) {
            pi += __shfl_xor_sync(0xffffffffu, pi, o);
            pf += __shfl_xor_sync(0xffffffffu, pf, o);
        }
        if (lane == 0) { s_red[warp] = pi; s_red[8 + warp] = pf; }
    }
    __syncthreads();
    if (tid == 0) {
        float it = s_red[0]+s_red[1]+s_red[2]+s_red[3]+s_red[4]+s_red[5]+s_red[6]+s_red[7] + bi[h];
        float ft = s_red[8]+s_red[9]+s_red[10]+s_red[11]+s_red[12]+s_red[13]+s_red[14]+s_red[15] + bf[h];
        float m0 = m_in[bh];
        float mt = fmaxf(ft + m0, it);
        s_ig = expf(it - mt);
        s_fg = expf(ft - mt + m0);
        m_out[bh] = mt;
    }
    __syncthreads();
    float ig = s_ig, fg = s_fg;

    float dp = 0.f;
    if (tid < HDIM) {
        float nt = fg * n_in[(size_t)bh * HDIM + tid] + ig * sk[tid];
        n_out[(size_t)bh * HDIM + tid] = nt;
        dp = nt * sq[tid];
    }
    for (int o = 16; o; o >>= 1) dp += __shfl_xor_sync(0xffffffffu, dp, o);
    if (lane == 0) s_red[warp] = dp;
    __syncthreads();
    if (tid == 0)
        s_den = fmaxf(s_red[0] + s_red[1] + s_red[2] + s_red[3], 1.0f);

    // c_t rows: 8 warps x 16 rows, 4 rows in flight, streaming loads/stores
    float4 kv = ((const float4*)sk)[lane];
    float4 qv = ((const float4*)sq)[lane];
    size_t base = (size_t)bh * HDIM * HDIM;
#pragma unroll
    for (int it4 = 0; it4 < 4; it4++) {
        int d[4];
        float4 cv[4];
#pragma unroll
        for (int j = 0; j < 4; j++) {
            d[j] = warp + (it4 * 4 + j) * 8;
            cv[j] = __ldcs((const float4*)(c_in + base + (size_t)d[j] * HDIM) + lane);
        }
        float a[4];
#pragma unroll
        for (int j = 0; j < 4; j++) {
            float iv = ig * sv[d[j]];
            float4 nc;
            nc.x = fg * cv[j].x + iv * kv.x;
            nc.y = fg * cv[j].y + iv * kv.y;
            nc.z = fg * cv[j].z + iv * kv.z;
            nc.w = fg * cv[j].w + iv * kv.w;
            __stcs((float4*)(c_out + base + (size_t)d[j] * HDIM) + lane, nc);
            a[j] = nc.x * qv.x + nc.y * qv.y + nc.z * qv.z + nc.w * qv.w;
        }
        for (int o = 16; o; o >>= 1) {
#pragma unroll
            for (int j = 0; j < 4; j++)
                a[j] += __shfl_xor_sync(0xffffffffu, a[j], o);
        }
        if (lane == 0) {
#pragma unroll
            for (int j = 0; j < 4; j++) sh[d[j]] = a[j];
        }
    }
    __syncthreads();

    float hv = 0.f;
    if (tid < HDIM)
        hv = g_o[b * HIDD + h * HDIM + tid] * sh[tid] / s_den;
    float s1 = hv, s2 = hv * hv;
    for (int o = 16; o; o >>= 1) {
        s1 += __shfl_xor_sync(0xffffffffu, s1, o);
        s2 += __shfl_xor_sync(0xffffffffu, s2, o);
    }
    if (lane == 0) { s_red[warp] = s1; s_red[8 + warp] = s2; }
    __syncthreads();
    if (tid == 0) {
        float m1 = (s_red[0] + s_red[1] + s_red[2] + s_red[3]) / (float)HDIM;
        float m2 = (s_red[8] + s_red[9] + s_red[10] + s_red[11]) / (float)HDIM;
        s_mu = m1;
        s_rstd = rsqrtf(m2 - m1 * m1 + EPSF);
    }
    __syncthreads();
    if (tid < HDIM) {
        int c = h * HDIM + tid;
        int gi = b * HIDD + c;
        float hn = (hv - s_mu) * s_rstd * gnw[c] + gnb[c];
        float r = g_rt[gi];
        float y = (hn + g_sk[gi]) * (r / (1.f + expf(-r)));
        g_yh[gi] = __float2half(y);
    }
}

// ---------------- host ---------------------------------------------------------
static void* sym_addr(const void* sym) {
    void* p = nullptr;
    cudaGetSymbolAddress(&p, sym);
    return p;
}

extern "C" void kernel_launch(void* const* d_in, const int* in_sizes, int n_in,
                              void* d_out, int out_size) {
    const float* seq    = (const float*)d_in[0];
    const float* c_tm1  = (const float*)d_in[1];
    const float* n_tm1  = (const float*)d_in[2];
    const float* m_tm1  = (const float*)d_in[3];
    const float* ln_w   = (const float*)d_in[4];
    const float* ln_b   = (const float*)d_in[5];
    const float* gn_w   = (const float*)d_in[6];
    const float* gn_b   = (const float*)d_in[7];
    const float* up_l_w = (const float*)d_in[8];
    const float* up_l_b = (const float*)d_in[9];
    const float* up_r_w = (const float*)d_in[10];
    const float* up_r_b = (const float*)d_in[11];
    const float* down_w = (const float*)d_in[12];
    const float* down_b = (const float*)d_in[13];
    const float* Wi_w   = (const float*)d_in[14];
    const float* Wi_b   = (const float*)d_in[15];
    const float* Wf_w   = (const float*)d_in[16];
    const float* Wf_b   = (const float*)d_in[17];
    const float* Wo_w   = (const float*)d_in[18];
    const float* Wo_b   = (const float*)d_in[19];
    const float* Wq_w   = (const float*)d_in[20];
    const float* Wq_b   = (const float*)d_in[21];
    const float* Wk_w   = (const float*)d_in[22];
    const float* Wk_b   = (const float*)d_in[23];
    const float* Wv_w   = (const float*)d_in[24];
    const float* Wv_b   = (const float*)d_in[25];
    const float* conv_w = (const float*)d_in[26];
    const float* conv_b = (const float*)d_in[27];
    const float* skip_w = (const float*)d_in[28];

    float* out   = (float*)d_out;
    float* c_out = out + (size_t)BB * DD;
    float* n_out = c_out + (size_t)BB * HH * HDIM * HDIM;
    float* m_out = n_out + (size_t)BB * HH * HDIM;

    float* p_rt = (float*)sym_addr(g_rt);
    float* p_q  = (float*)sym_addr(g_q);
    float* p_k  = (float*)sym_addr(g_k);
    float* p_v  = (float*)sym_addr(g_v);
    float* p_o  = (float*)sym_addr(g_o);
    float* p_sk = (float*)sym_addr(g_sk);

    __half* wf  = (__half*)sym_addr(g_wf);
    __half* xnh = (__half*)sym_addr(g_xnh);
    __half* xth = (__half*)sym_addr(g_xth);
    __half* xch = (__half*)sym_addr(g_xch);
    __half* yh  = (__half*)sym_addr(g_yh);

    cudaFuncSetAttribute(tgemm, cudaFuncAttributeMaxDynamicSharedMemorySize, DYN_SMEM);

    static cudaStream_t s2 = nullptr;
    static cudaEvent_t eFork = nullptr, e1 = nullptr, e2 = nullptr;
    if (s2 == nullptr) {
        cudaStreamCreateWithFlags(&s2, cudaStreamNonBlocking);
        cudaEventCreateWithFlags(&eFork, cudaEventDisableTiming);
        cudaEventCreateWithFlags(&e1, cudaEventDisableTiming);
        cudaEventCreateWithFlags(&e2, cudaEventDisableTiming);
    }

    const float kscale = 1.0f / sqrtf((float)HDIM);

    cudaEventRecord(eFork, 0);
    cudaStreamWaitEvent(s2, eFork, 0);

    {
        SArgs a; a.nseg = 2;
        a.s[0] = { up_l_w, wf + OFF_UPL, 2048 };
        a.s[1] = { up_r_w, wf + OFF_UPR, 1024 };
        split_kernel<<<3072, 256, 0, s2>>>(a);
        cudaEventRecord(e1, s2);
    }
    {
        SArgs a; a.nseg = 6;
        a.s[0] = { Wq_w,   wf + OFF_Q,    2048 };
        a.s[1] = { Wk_w,   wf + OFF_K,    2048 };
        a.s[2] = { Wv_w,   wf + OFF_V,    2048 };
        a.s[3] = { Wo_w,   wf + OFF_O,    2048 };
        a.s[4] = { skip_w, wf + OFF_SKIP, 2048 };
        a.s[5] = { down_w, wf + OFF_DOWN, 1024 };
        split_kernel<<<11264, 256, 0, s2>>>(a);
        cudaEventRecord(e2, s2);
    }

    ln_kernel<<<BB, 256>>>(seq, ln_w, ln_b);

    cudaStreamWaitEvent(0, e1, 0);
    {
        TArgs a; a.nseg = 2; a.K = DD;
        a.s[0] = { xnh, wf + OFF_UPL, up_l_b, nullptr, nullptr, xth, 1.f, 0, PP / TBN,   PP   };
        a.s[1] = { xnh, wf + OFF_UPR, up_r_b, nullptr, p_rt, nullptr, 1.f, 0, HIDD / TBN, HIDD };
        tgemm<<<dim3(PP / TBN + HIDD / TBN, BB / TBM), 128, DYN_SMEM>>>(a);
    }

    conv_kernel<<<(BB * PP / 8) / 256, 256>>>(conv_w, conv_b);

    cudaStreamWaitEvent(0, e2, 0);
    {
        TArgs a; a.nseg = 5; a.K = PP;
        a.s[0] = { xch, wf + OFF_Q,    Wq_b,    nullptr, p_q,  nullptr, 1.f,    0, HIDD / TBN, HIDD };
        a.s[1] = { xch, wf + OFF_K,    Wk_b,    nullptr, p_k,  nullptr, kscale, 0, HIDD / TBN, HIDD };
        a.s[2] = { xth, wf + OFF_V,    Wv_b,    nullptr, p_v,  nullptr, 1.f,    0, HIDD / TBN, HIDD };
        a.s[3] = { xth, wf + OFF_O,    Wo_b,    nullptr, p_o,  nullptr, 1.f,    1, HIDD / TBN, HIDD };
        a.s[4] = { xch, wf + OFF_SKIP, nullptr, nullptr, p_sk, nullptr, 1.f,    0, HIDD / TBN, HIDD };
        tgemm<<<dim3(5 * (HIDD / TBN), BB / TBM), 128, DYN_SMEM>>>(a);
    }

    cell_kernel<<<BB * HH, 256>>>(c_tm1, n_tm1, m_tm1, gn_w, gn_b,
                                  Wi_w, Wi_b, Wf_w, Wf_b,
                                  c_out, n_out, m_out);

    {
        TArgs a; a.nseg = 1; a.K = HIDD;
        a.s[0] = { yh, wf + OFF_DOWN, down_b, seq, out, nullptr, 1.f, 0, DD / TBN, DD };
        tgemm<<<dim3(DD / TBN, BB / TBM), 128, DYN_SMEM>>>(a);
    }
}